// round 14
// baseline (speedup 1.0000x reference)
#include <cuda_runtime.h>
#include <cuda_fp16.h>
#include <cstdint>

// Problem constants
#define IN_F   4096
#define OUT_F  12288
#define NWORDS 1536
#define NTOK   8192
#define GROUP  128

// GEMM tiling (converged shape)
#define BM 128
#define BN 128
#define BK 64
#define LDA 72     // BK + 8 halves pad (144B row: LDSM conflict-free)
#define LDB 136    // BN + 8 halves pad (272B row: LDSM conflict-free)
#define KT  (IN_F / BK)        // 64
#define STAGES 3
#define SMEM_BYTES (STAGES * (BM * LDA + BK * LDB) * 2)  // 107520 -> 2 CTAs/SM

#define NTILE (OUT_F / BN)     // 96
#define SW 8
#define TOTAL_TILES ((NTOK / BM) * NTILE)  // 6144
#define GEMM_GRID 304          // 2 CTAs/SM x 152 SMs (GB300)

// Prep kernel block split
#define DEQ_BLOCKS  3072
#define CONV_BLOCKS 32768
#define PREP_BLOCKS (DEQ_BLOCKS + CONV_BLOCKS)

__device__ __half g_X[(size_t)NTOK * IN_F];    // [M][K] fp16
__device__ __half g_W[(size_t)IN_F * OUT_F];   // [K][N] fp16

// ---------------------------------------------------------------------------
// int4x8 word -> 4x half2 {1024+n}, LOP3 magic + PRMT reorder.
// ---------------------------------------------------------------------------
__device__ __forceinline__ void unpack8(uint32_t q, uint32_t r[4]) {
    uint32_t p04, p15, p26, p37;
    asm("lop3.b32 %0, %1, 0x000F000F, 0x64006400, 0xEA;" : "=r"(p04) : "r"(q));
    asm("lop3.b32 %0, %1, 0x000F000F, 0x64006400, 0xEA;" : "=r"(p15) : "r"(q >> 4));
    asm("lop3.b32 %0, %1, 0x000F000F, 0x64006400, 0xEA;" : "=r"(p26) : "r"(q >> 8));
    asm("lop3.b32 %0, %1, 0x000F000F, 0x64006400, 0xEA;" : "=r"(p37) : "r"(q >> 12));
    asm("prmt.b32 %0, %1, %2, 0x5410;" : "=r"(r[0]) : "r"(p04), "r"(p15));
    asm("prmt.b32 %0, %1, %2, 0x5410;" : "=r"(r[1]) : "r"(p26), "r"(p37));
    asm("prmt.b32 %0, %1, %2, 0x7632;" : "=r"(r[2]) : "r"(p04), "r"(p15));
    asm("prmt.b32 %0, %1, %2, 0x7632;" : "=r"(r[3]) : "r"(p26), "r"(p37));
}

// ---------------------------------------------------------------------------
// Prep: blocks [0, DEQ_BLOCKS) dequantize W (bit-exact vs reference); rest
// convert X fp32->fp16 (exact).
// ---------------------------------------------------------------------------
__global__ void prep_kernel(const float* __restrict__ xf,
                            const int* __restrict__ qw,
                            const float* __restrict__ scales,
                            const int* __restrict__ qz) {
    if (blockIdx.x < DEQ_BLOCKS) {
        int tid = blockIdx.x * 256 + threadIdx.x;
        int c  = tid % NWORDS;
        int kb = tid / NWORDS;
        int k0 = kb * 8;
        int g  = kb >> 4;

        uint32_t zr[4];
        unpack8(((const uint32_t*)qz)[g * NWORDS + c], zr);
        __half2 hz[4];
        hz[0] = *(__half2*)&zr[0]; hz[1] = *(__half2*)&zr[1];
        hz[2] = *(__half2*)&zr[2]; hz[3] = *(__half2*)&zr[3];

        const float* sp = scales + (size_t)g * OUT_F + c * 8;
        float4 s0 = *(const float4*)sp;
        float4 s1 = *(const float4*)(sp + 4);
        __half2 hs[4];
        hs[0] = __floats2half2_rn(s0.x, s0.y);
        hs[1] = __floats2half2_rn(s0.z, s0.w);
        hs[2] = __floats2half2_rn(s1.x, s1.y);
        hs[3] = __floats2half2_rn(s1.z, s1.w);

#pragma unroll
        for (int i = 0; i < 8; i++) {
            uint32_t qr[4];
            unpack8(((const uint32_t*)qw)[(size_t)(k0 + i) * NWORDS + c], qr);
            uint32_t o[4];
#pragma unroll
            for (int j = 0; j < 4; j++) {
                __half2 hq = *(__half2*)&qr[j];
                __half2 w = __hmul2(__hsub2(hq, hz[j]), hs[j]);
                o[j] = *(uint32_t*)&w;
            }
            *(uint4*)(g_W + (size_t)(k0 + i) * OUT_F + c * 8) = *(uint4*)o;
        }
    } else {
        size_t i = (size_t)((blockIdx.x - DEQ_BLOCKS) * 256 + threadIdx.x) * 4;
        float4 v = *(const float4*)(xf + i);
        __half h[4];
        h[0] = __float2half_rn(v.x); h[1] = __float2half_rn(v.y);
        h[2] = __float2half_rn(v.z); h[3] = __float2half_rn(v.w);
        *(uint2*)(g_X + i) = *(uint2*)h;
    }
}

// ---------------------------------------------------------------------------
// Persistent GEMM: 304 CTAs, each owns tiles {bid, bid+304, ...}. The 3-stage
// cp.async pipeline ROLLS across tile boundaries: next tile's stages are in
// flight while this tile's epilogue runs (no per-tile prologue drain).
// ---------------------------------------------------------------------------
__device__ __forceinline__ void cp16(uint32_t saddr, const void* gptr) {
    asm volatile("cp.async.cg.shared.global [%0], [%1], 16;\n"
                 :: "r"(saddr), "l"(gptr));
}
__device__ __forceinline__ void ldsm_x4(uint32_t& r0, uint32_t& r1,
                                        uint32_t& r2, uint32_t& r3, uint32_t a) {
    asm volatile("ldmatrix.sync.aligned.m8n8.x4.shared.b16 {%0,%1,%2,%3}, [%4];"
                 : "=r"(r0), "=r"(r1), "=r"(r2), "=r"(r3) : "r"(a));
}
__device__ __forceinline__ void ldsm_x4t(uint32_t& r0, uint32_t& r1,
                                         uint32_t& r2, uint32_t& r3, uint32_t a) {
    asm volatile("ldmatrix.sync.aligned.m8n8.x4.trans.shared.b16 {%0,%1,%2,%3}, [%4];"
                 : "=r"(r0), "=r"(r1), "=r"(r2), "=r"(r3) : "r"(a));
}
__device__ __forceinline__ void map_tile(int tile, int& bm_, int& bn_) {
    int super = tile / (SW * NTILE);
    int r = tile - super * (SW * NTILE);
    bm_ = (super * SW + (r & 7)) * BM;   // r % SW
    bn_ = (r >> 3) * BN;                 // r / SW
}

__global__ void __launch_bounds__(256, 2)
gemm_kernel(const float* __restrict__ biasf,
            float* __restrict__ out) {
    extern __shared__ __half smem[];
    __half* sA = smem;
    __half* sB = smem + STAGES * BM * LDA;

    const int t = threadIdx.x;
    const uint32_t sA_base = (uint32_t)__cvta_generic_to_shared(sA);
    const uint32_t sB_base = (uint32_t)__cvta_generic_to_shared(sB);

    const int warp = t >> 5;
    const int lane = t & 31;
    const int wm = (warp & 3) * 32;
    const int wn = (warp >> 2) * 64;
    const int gr = lane >> 2;
    const int gc2 = (lane & 3) * 2;

    const int aRow = wm + (((lane >> 3) & 1) << 3) + (lane & 7);
    const int aCol = ((lane >> 4) << 3);
    const int bRow = (lane & 15);
    const int bCol = wn + ((lane >> 4) << 3);

    auto loadTile = [&](int s, int bm_, int bn_, int k0) {
#pragma unroll
        for (int it = 0; it < 4; it++) {
            int chunk = t + it * 256;
            int row = chunk >> 3, cc = chunk & 7;
            cp16(sA_base + (uint32_t)(((s * BM + row) * LDA + cc * 8) * 2),
                 g_X + (size_t)(bm_ + row) * IN_F + k0 + cc * 8);
        }
#pragma unroll
        for (int it = 0; it < 4; it++) {
            int chunk = t + it * 256;
            int row = chunk >> 4, cc = chunk & 15;
            cp16(sB_base + (uint32_t)(((s * BK + row) * LDB + cc * 8) * 2),
                 g_W + (size_t)(k0 + row) * OUT_F + bn_ + cc * 8);
        }
        asm volatile("cp.async.commit_group;\n" ::: "memory");
    };

    // Load-stream state (runs ahead of compute by 2 kt positions).
    int lTile = blockIdx.x, lKt = 0;
    int lBm, lBn;
    map_tile(lTile, lBm, lBn);
    auto advanceLd = [&]() {
        if (++lKt == KT) {
            lKt = 0;
            lTile += GEMM_GRID;
            if (lTile < TOTAL_TILES) map_tile(lTile, lBm, lBn);
        }
    };

    if (lTile < TOTAL_TILES) {
        loadTile(0, lBm, lBn, lKt * BK); advanceLd();
        loadTile(1, lBm, lBn, lKt * BK); advanceLd();
    }
    int sCur = 0, sNext = 2;

    float acc[2][8][4];

    for (int cTile = blockIdx.x; cTile < TOTAL_TILES; cTile += GEMM_GRID) {
        int bm, bn;
        map_tile(cTile, bm, bn);

#pragma unroll
        for (int mi = 0; mi < 2; mi++)
#pragma unroll
            for (int ni = 0; ni < 8; ni++)
#pragma unroll
                for (int i = 0; i < 4; i++) acc[mi][ni][i] = 0.f;

        for (int kt = 0; kt < KT; kt++) {
            if (lTile < TOTAL_TILES)
                asm volatile("cp.async.wait_group 1;\n" ::: "memory");
            else
                asm volatile("cp.async.wait_group 0;\n" ::: "memory");
            __syncthreads();

            if (lTile < TOTAL_TILES) {
                loadTile(sNext, lBm, lBn, lKt * BK);
                advanceLd();
                if (++sNext == STAGES) sNext = 0;
            }

            const uint32_t aSt = sA_base + (uint32_t)(sCur * BM * LDA * 2);
            const uint32_t bSt = sB_base + (uint32_t)(sCur * BK * LDB * 2);
            if (++sCur == STAGES) sCur = 0;

#pragma unroll
            for (int ks = 0; ks < 4; ks++) {
                const int kb = ks * 16;

                uint32_t a[2][4];
#pragma unroll
                for (int mi = 0; mi < 2; mi++) {
                    uint32_t addr = aSt +
                        (uint32_t)(((aRow + mi * 16) * LDA + aCol + kb) * 2);
                    ldsm_x4(a[mi][0], a[mi][1], a[mi][2], a[mi][3], addr);
                }

                uint32_t b[8][2];
#pragma unroll
                for (int p = 0; p < 4; p++) {
                    uint32_t addr = bSt +
                        (uint32_t)(((bRow + kb) * LDB + bCol + p * 16) * 2);
                    ldsm_x4t(b[2 * p][0], b[2 * p][1],
                             b[2 * p + 1][0], b[2 * p + 1][1], addr);
                }

#pragma unroll
                for (int mi = 0; mi < 2; mi++)
#pragma unroll
                    for (int ni = 0; ni < 8; ni++) {
                        asm volatile(
                            "mma.sync.aligned.m16n8k16.row.col.f32.f16.f16.f32 "
                            "{%0,%1,%2,%3}, {%4,%5,%6,%7}, {%8,%9}, {%0,%1,%2,%3};\n"
                            : "+f"(acc[mi][ni][0]), "+f"(acc[mi][ni][1]),
                              "+f"(acc[mi][ni][2]), "+f"(acc[mi][ni][3])
                            : "r"(a[mi][0]), "r"(a[mi][1]),
                              "r"(a[mi][2]), "r"(a[mi][3]),
                              "r"(b[ni][0]), "r"(b[ni][1]));
                    }
            }
        }

        // Epilogue (overlaps the already-in-flight loads of the next tile).
        __half bh[16];
#pragma unroll
        for (int ni = 0; ni < 8; ni++) {
            bh[2 * ni]     = __float2half_rn(biasf[bn + wn + ni * 8 + gc2]);
            bh[2 * ni + 1] = __float2half_rn(biasf[bn + wn + ni * 8 + gc2 + 1]);
        }
#pragma unroll
        for (int mi = 0; mi < 2; mi++) {
            int row = bm + wm + mi * 16 + gr;
#pragma unroll
            for (int ni = 0; ni < 8; ni++) {
                int col = bn + wn + ni * 8 + gc2;
                float2 v;
                v.x = __half2float(__hadd(__float2half_rn(acc[mi][ni][0]), bh[2 * ni]));
                v.y = __half2float(__hadd(__float2half_rn(acc[mi][ni][1]), bh[2 * ni + 1]));
                *(float2*)(out + (size_t)row * OUT_F + col) = v;
                v.x = __half2float(__hadd(__float2half_rn(acc[mi][ni][2]), bh[2 * ni]));
                v.y = __half2float(__hadd(__float2half_rn(acc[mi][ni][3]), bh[2 * ni + 1]));
                *(float2*)(out + (size_t)(row + 8) * OUT_F + col) = v;
            }
        }
    }
}

// ---------------------------------------------------------------------------
// Launch. Inputs resolved BY ELEMENT COUNT. fp16 tensors arrive as FLOAT32
// (harness upcast); output FLOAT32 [8192][12288].
// ---------------------------------------------------------------------------
extern "C" void kernel_launch(void* const* d_in, const int* in_sizes, int n_in,
                              void* d_out, int out_size) {
    const float* x      = nullptr;
    const int*   qw     = nullptr;
    const float* scales = nullptr;
    const int*   qz     = nullptr;
    const float* bias   = nullptr;

    for (int i = 0; i < n_in; i++) {
        switch (in_sizes[i]) {
            case 33554432: x      = (const float*)d_in[i]; break;
            case  6291456: qw     = (const int*)  d_in[i]; break;
            case   393216: scales = (const float*)d_in[i]; break;
            case    49152: qz     = (const int*)  d_in[i]; break;
            case    12288: bias   = (const float*)d_in[i]; break;
            default: break;
        }
    }
    float* out = (float*)d_out;

    prep_kernel<<<PREP_BLOCKS, 256>>>(x, qw, scales, qz);

    cudaFuncSetAttribute(gemm_kernel,
                         cudaFuncAttributeMaxDynamicSharedMemorySize, SMEM_BYTES);
    gemm_kernel<<<GEMM_GRID, 256, SMEM_BYTES>>>(bias, out);
}

// round 15
// speedup vs baseline: 1.1714x; 1.1714x over previous
#include <cuda_runtime.h>
#include <cuda_fp16.h>
#include <cstdint>

// Problem constants
#define IN_F   4096
#define OUT_F  12288
#define NWORDS 1536
#define NTOK   8192
#define GROUP  128

// GEMM tiling (converged shape)
#define BM 128
#define BN 128
#define BK 64
#define LDA 72     // BK + 8 halves pad (144B row: LDSM conflict-free)
#define LDB 136    // BN + 8 halves pad (272B row: LDSM conflict-free)
#define KT  (IN_F / BK)  // 64
#define STAGES 3
#define SMEM_BYTES (STAGES * (BM * LDA + BK * LDB) * 2)  // 107520 -> 2 CTAs/SM

// Prep kernel block split
#define DEQ_BLOCKS  3072
#define CONV_BLOCKS 32768
#define PREP_BLOCKS (DEQ_BLOCKS + CONV_BLOCKS)

__device__ __half g_X[(size_t)NTOK * IN_F];    // [M][K] fp16
__device__ __half g_W[(size_t)IN_F * OUT_F];   // [K][N] fp16

// ---------------------------------------------------------------------------
// int4x8 word -> 4x half2 {1024+n}, LOP3 magic + PRMT reorder.
// ---------------------------------------------------------------------------
__device__ __forceinline__ void unpack8(uint32_t q, uint32_t r[4]) {
    uint32_t p04, p15, p26, p37;
    asm("lop3.b32 %0, %1, 0x000F000F, 0x64006400, 0xEA;" : "=r"(p04) : "r"(q));
    asm("lop3.b32 %0, %1, 0x000F000F, 0x64006400, 0xEA;" : "=r"(p15) : "r"(q >> 4));
    asm("lop3.b32 %0, %1, 0x000F000F, 0x64006400, 0xEA;" : "=r"(p26) : "r"(q >> 8));
    asm("lop3.b32 %0, %1, 0x000F000F, 0x64006400, 0xEA;" : "=r"(p37) : "r"(q >> 12));
    asm("prmt.b32 %0, %1, %2, 0x5410;" : "=r"(r[0]) : "r"(p04), "r"(p15));
    asm("prmt.b32 %0, %1, %2, 0x5410;" : "=r"(r[1]) : "r"(p26), "r"(p37));
    asm("prmt.b32 %0, %1, %2, 0x7632;" : "=r"(r[2]) : "r"(p04), "r"(p15));
    asm("prmt.b32 %0, %1, %2, 0x7632;" : "=r"(r[3]) : "r"(p26), "r"(p37));
}

// ---------------------------------------------------------------------------
// Prep: blocks [0, DEQ_BLOCKS) dequantize W (bit-exact vs reference); rest
// convert X fp32->fp16 (exact).
// ---------------------------------------------------------------------------
__global__ void prep_kernel(const float* __restrict__ xf,
                            const int* __restrict__ qw,
                            const float* __restrict__ scales,
                            const int* __restrict__ qz) {
    if (blockIdx.x < DEQ_BLOCKS) {
        int tid = blockIdx.x * 256 + threadIdx.x;
        int c  = tid % NWORDS;
        int kb = tid / NWORDS;
        int k0 = kb * 8;
        int g  = kb >> 4;

        uint32_t zr[4];
        unpack8(((const uint32_t*)qz)[g * NWORDS + c], zr);
        __half2 hz[4];
        hz[0] = *(__half2*)&zr[0]; hz[1] = *(__half2*)&zr[1];
        hz[2] = *(__half2*)&zr[2]; hz[3] = *(__half2*)&zr[3];

        const float* sp = scales + (size_t)g * OUT_F + c * 8;
        float4 s0 = *(const float4*)sp;
        float4 s1 = *(const float4*)(sp + 4);
        __half2 hs[4];
        hs[0] = __floats2half2_rn(s0.x, s0.y);
        hs[1] = __floats2half2_rn(s0.z, s0.w);
        hs[2] = __floats2half2_rn(s1.x, s1.y);
        hs[3] = __floats2half2_rn(s1.z, s1.w);

#pragma unroll
        for (int i = 0; i < 8; i++) {
            uint32_t qr[4];
            unpack8(((const uint32_t*)qw)[(size_t)(k0 + i) * NWORDS + c], qr);
            uint32_t o[4];
#pragma unroll
            for (int j = 0; j < 4; j++) {
                __half2 hq = *(__half2*)&qr[j];
                __half2 w = __hmul2(__hsub2(hq, hz[j]), hs[j]);
                o[j] = *(uint32_t*)&w;
            }
            *(uint4*)(g_W + (size_t)(k0 + i) * OUT_F + c * 8) = *(uint4*)o;
        }
    } else {
        size_t i = (size_t)((blockIdx.x - DEQ_BLOCKS) * 256 + threadIdx.x) * 4;
        float4 v = *(const float4*)(xf + i);
        __half h[4];
        h[0] = __float2half_rn(v.x); h[1] = __float2half_rn(v.y);
        h[2] = __float2half_rn(v.z); h[3] = __float2half_rn(v.w);
        *(uint2*)(g_X + i) = *(uint2*)h;
    }
}

// ---------------------------------------------------------------------------
// GEMM: 128x128x64, 256 thr, 2 CTAs/SM, 3-stage cp.async. loadTile issue is
// DEFERRED to after ks=0's fragment loads + mma burst, so the tensor pipe
// refills immediately after the barrier instead of waiting out the cp.async
// addressing burst.
// ---------------------------------------------------------------------------
__device__ __forceinline__ void cp16(uint32_t saddr, const void* gptr) {
    asm volatile("cp.async.cg.shared.global [%0], [%1], 16;\n"
                 :: "r"(saddr), "l"(gptr));
}
__device__ __forceinline__ void ldsm_x4(uint32_t& r0, uint32_t& r1,
                                        uint32_t& r2, uint32_t& r3, uint32_t a) {
    asm volatile("ldmatrix.sync.aligned.m8n8.x4.shared.b16 {%0,%1,%2,%3}, [%4];"
                 : "=r"(r0), "=r"(r1), "=r"(r2), "=r"(r3) : "r"(a));
}
__device__ __forceinline__ void ldsm_x4t(uint32_t& r0, uint32_t& r1,
                                         uint32_t& r2, uint32_t& r3, uint32_t a) {
    asm volatile("ldmatrix.sync.aligned.m8n8.x4.trans.shared.b16 {%0,%1,%2,%3}, [%4];"
                 : "=r"(r0), "=r"(r1), "=r"(r2), "=r"(r3) : "r"(a));
}

__global__ void __launch_bounds__(256, 2)
gemm_kernel(const float* __restrict__ biasf,
            float* __restrict__ out) {
    extern __shared__ __half smem[];
    __half* sA = smem;
    __half* sB = smem + STAGES * BM * LDA;

    const int t = threadIdx.x;

    const int NTILE = OUT_F / BN;  // 96
    const int SW = 8;
    int bid = blockIdx.x;
    int super = bid / (SW * NTILE);
    int r = bid - super * (SW * NTILE);
    const int bm = (super * SW + (r % SW)) * BM;
    const int bn = (r / SW) * BN;

    const uint32_t sA_base = (uint32_t)__cvta_generic_to_shared(sA);
    const uint32_t sB_base = (uint32_t)__cvta_generic_to_shared(sB);

    const int warp = t >> 5;
    const int lane = t & 31;
    const int wm = (warp & 3) * 32;
    const int wn = (warp >> 2) * 64;
    const int gr = lane >> 2;
    const int gc2 = (lane & 3) * 2;

    const int aRow = wm + (((lane >> 3) & 1) << 3) + (lane & 7);
    const int aCol = ((lane >> 4) << 3);
    const int bRow = (lane & 15);
    const int bCol = wn + ((lane >> 4) << 3);

    float acc[2][8][4];
#pragma unroll
    for (int mi = 0; mi < 2; mi++)
#pragma unroll
        for (int ni = 0; ni < 8; ni++)
#pragma unroll
            for (int i = 0; i < 4; i++) acc[mi][ni][i] = 0.f;

    auto loadTile = [&](int s, int k0) {
#pragma unroll
        for (int it = 0; it < 4; it++) {
            int chunk = t + it * 256;
            int row = chunk >> 3, cc = chunk & 7;
            cp16(sA_base + (uint32_t)(((s * BM + row) * LDA + cc * 8) * 2),
                 g_X + (size_t)(bm + row) * IN_F + k0 + cc * 8);
        }
#pragma unroll
        for (int it = 0; it < 4; it++) {
            int chunk = t + it * 256;
            int row = chunk >> 4, cc = chunk & 15;
            cp16(sB_base + (uint32_t)(((s * BK + row) * LDB + cc * 8) * 2),
                 g_W + (size_t)(k0 + row) * OUT_F + bn + cc * 8);
        }
        asm volatile("cp.async.commit_group;\n" ::: "memory");
    };

    loadTile(0, 0);
    loadTile(1, BK);

    for (int kt = 0; kt < KT; kt++) {
        if (kt < KT - 1) asm volatile("cp.async.wait_group 1;\n" ::: "memory");
        else             asm volatile("cp.async.wait_group 0;\n" ::: "memory");
        __syncthreads();

        const int s = kt % STAGES;
        const uint32_t aSt = sA_base + (uint32_t)(s * BM * LDA * 2);
        const uint32_t bSt = sB_base + (uint32_t)(s * BK * LDB * 2);

        // A-fragment ks-pipeline (as in best R12).
        uint32_t a[2][2][4];
#pragma unroll
        for (int mi = 0; mi < 2; mi++) {
            uint32_t addr = aSt + (uint32_t)(((aRow + mi * 16) * LDA + aCol) * 2);
            ldsm_x4(a[0][mi][0], a[0][mi][1], a[0][mi][2], a[0][mi][3], addr);
        }

#pragma unroll
        for (int ks = 0; ks < 4; ks++) {
            const int kb = ks * 16;
            const int cur = ks & 1, nxt = cur ^ 1;

            // Deferred tile load: issue AFTER ks=0's fragments + mma burst,
            // so post-barrier tensor refill isn't blocked by cp.async issue.
            if (ks == 1 && kt + 2 < KT)
                loadTile((kt + 2) % STAGES, (kt + 2) * BK);

            if (ks < 3) {
#pragma unroll
                for (int mi = 0; mi < 2; mi++) {
                    uint32_t addr = aSt +
                        (uint32_t)(((aRow + mi * 16) * LDA + aCol + kb + 16) * 2);
                    ldsm_x4(a[nxt][mi][0], a[nxt][mi][1],
                            a[nxt][mi][2], a[nxt][mi][3], addr);
                }
            }

            uint32_t b[8][2];
#pragma unroll
            for (int p = 0; p < 4; p++) {
                uint32_t addr = bSt +
                    (uint32_t)(((bRow + kb) * LDB + bCol + p * 16) * 2);
                ldsm_x4t(b[2 * p][0], b[2 * p][1],
                         b[2 * p + 1][0], b[2 * p + 1][1], addr);
            }

#pragma unroll
            for (int mi = 0; mi < 2; mi++)
#pragma unroll
                for (int ni = 0; ni < 8; ni++) {
                    asm volatile(
                        "mma.sync.aligned.m16n8k16.row.col.f32.f16.f16.f32 "
                        "{%0,%1,%2,%3}, {%4,%5,%6,%7}, {%8,%9}, {%0,%1,%2,%3};\n"
                        : "+f"(acc[mi][ni][0]), "+f"(acc[mi][ni][1]),
                          "+f"(acc[mi][ni][2]), "+f"(acc[mi][ni][3])
                        : "r"(a[cur][mi][0]), "r"(a[cur][mi][1]),
                          "r"(a[cur][mi][2]), "r"(a[cur][mi][3]),
                          "r"(b[ni][0]), "r"(b[ni][1]));
                }
        }
    }

    __half bh[16];
#pragma unroll
    for (int ni = 0; ni < 8; ni++) {
        bh[2 * ni]     = __float2half_rn(biasf[bn + wn + ni * 8 + gc2]);
        bh[2 * ni + 1] = __float2half_rn(biasf[bn + wn + ni * 8 + gc2 + 1]);
    }
#pragma unroll
    for (int mi = 0; mi < 2; mi++) {
        int row = bm + wm + mi * 16 + gr;
#pragma unroll
        for (int ni = 0; ni < 8; ni++) {
            int col = bn + wn + ni * 8 + gc2;
            float2 v;
            v.x = __half2float(__hadd(__float2half_rn(acc[mi][ni][0]), bh[2 * ni]));
            v.y = __half2float(__hadd(__float2half_rn(acc[mi][ni][1]), bh[2 * ni + 1]));
            *(float2*)(out + (size_t)row * OUT_F + col) = v;
            v.x = __half2float(__hadd(__float2half_rn(acc[mi][ni][2]), bh[2 * ni]));
            v.y = __half2float(__hadd(__float2half_rn(acc[mi][ni][3]), bh[2 * ni + 1]));
            *(float2*)(out + (size_t)(row + 8) * OUT_F + col) = v;
        }
    }
}

// ---------------------------------------------------------------------------
// Launch. Inputs resolved BY ELEMENT COUNT. fp16 tensors arrive as FLOAT32
// (harness upcast); output FLOAT32 [8192][12288].
// ---------------------------------------------------------------------------
extern "C" void kernel_launch(void* const* d_in, const int* in_sizes, int n_in,
                              void* d_out, int out_size) {
    const float* x      = nullptr;
    const int*   qw     = nullptr;
    const float* scales = nullptr;
    const int*   qz     = nullptr;
    const float* bias   = nullptr;

    for (int i = 0; i < n_in; i++) {
        switch (in_sizes[i]) {
            case 33554432: x      = (const float*)d_in[i]; break;
            case  6291456: qw     = (const int*)  d_in[i]; break;
            case   393216: scales = (const float*)d_in[i]; break;
            case    49152: qz     = (const int*)  d_in[i]; break;
            case    12288: bias   = (const float*)d_in[i]; break;
            default: break;
        }
    }
    float* out = (float*)d_out;

    prep_kernel<<<PREP_BLOCKS, 256>>>(x, qw, scales, qz);

    cudaFuncSetAttribute(gemm_kernel,
                         cudaFuncAttributeMaxDynamicSharedMemorySize, SMEM_BYTES);
    const int grid = (NTOK / BM) * (OUT_F / BN);  // 6144
    gemm_kernel<<<grid, 256, SMEM_BYTES>>>(bias, out);
}

// round 16
// speedup vs baseline: 1.2005x; 1.0249x over previous
#include <cuda_runtime.h>
#include <cuda_fp16.h>
#include <cstdint>

// Problem constants
#define IN_F   4096
#define OUT_F  12288
#define NWORDS 1536
#define NTOK   8192
#define GROUP  128

// GEMM tiling (converged shape)
#define BM 128
#define BN 128
#define BK 64
#define LDA 72     // BK + 8 halves pad (144B row: LDSM conflict-free)
#define LDB 136    // BN + 8 halves pad (272B row: LDSM conflict-free)
#define KT  (IN_F / BK)  // 64
#define STAGES 3
#define SMEM_BYTES (STAGES * (BM * LDA + BK * LDB) * 2)  // 107520 -> 2 CTAs/SM

// Prep kernel block split
#define DEQ_BLOCKS  3072
#define CONV_BLOCKS 32768
#define PREP_BLOCKS (DEQ_BLOCKS + CONV_BLOCKS)

__device__ __half g_X[(size_t)NTOK * IN_F];    // [M][K] fp16
__device__ __half g_W[(size_t)IN_F * OUT_F];   // [K][N] fp16

// ---------------------------------------------------------------------------
// int4x8 word -> 4x half2 {1024+n}, LOP3 magic + PRMT reorder.
// ---------------------------------------------------------------------------
__device__ __forceinline__ void unpack8(uint32_t q, uint32_t r[4]) {
    uint32_t p04, p15, p26, p37;
    asm("lop3.b32 %0, %1, 0x000F000F, 0x64006400, 0xEA;" : "=r"(p04) : "r"(q));
    asm("lop3.b32 %0, %1, 0x000F000F, 0x64006400, 0xEA;" : "=r"(p15) : "r"(q >> 4));
    asm("lop3.b32 %0, %1, 0x000F000F, 0x64006400, 0xEA;" : "=r"(p26) : "r"(q >> 8));
    asm("lop3.b32 %0, %1, 0x000F000F, 0x64006400, 0xEA;" : "=r"(p37) : "r"(q >> 12));
    asm("prmt.b32 %0, %1, %2, 0x5410;" : "=r"(r[0]) : "r"(p04), "r"(p15));
    asm("prmt.b32 %0, %1, %2, 0x5410;" : "=r"(r[1]) : "r"(p26), "r"(p37));
    asm("prmt.b32 %0, %1, %2, 0x7632;" : "=r"(r[2]) : "r"(p04), "r"(p15));
    asm("prmt.b32 %0, %1, %2, 0x7632;" : "=r"(r[3]) : "r"(p26), "r"(p37));
}

// ---------------------------------------------------------------------------
// Prep: blocks [0, DEQ_BLOCKS) dequantize W (bit-exact vs reference); rest
// convert X fp32->fp16 (exact).
// ---------------------------------------------------------------------------
__global__ void prep_kernel(const float* __restrict__ xf,
                            const int* __restrict__ qw,
                            const float* __restrict__ scales,
                            const int* __restrict__ qz) {
    if (blockIdx.x < DEQ_BLOCKS) {
        int tid = blockIdx.x * 256 + threadIdx.x;
        int c  = tid % NWORDS;
        int kb = tid / NWORDS;
        int k0 = kb * 8;
        int g  = kb >> 4;

        uint32_t zr[4];
        unpack8(((const uint32_t*)qz)[g * NWORDS + c], zr);
        __half2 hz[4];
        hz[0] = *(__half2*)&zr[0]; hz[1] = *(__half2*)&zr[1];
        hz[2] = *(__half2*)&zr[2]; hz[3] = *(__half2*)&zr[3];

        const float* sp = scales + (size_t)g * OUT_F + c * 8;
        float4 s0 = *(const float4*)sp;
        float4 s1 = *(const float4*)(sp + 4);
        __half2 hs[4];
        hs[0] = __floats2half2_rn(s0.x, s0.y);
        hs[1] = __floats2half2_rn(s0.z, s0.w);
        hs[2] = __floats2half2_rn(s1.x, s1.y);
        hs[3] = __floats2half2_rn(s1.z, s1.w);

#pragma unroll
        for (int i = 0; i < 8; i++) {
            uint32_t qr[4];
            unpack8(((const uint32_t*)qw)[(size_t)(k0 + i) * NWORDS + c], qr);
            uint32_t o[4];
#pragma unroll
            for (int j = 0; j < 4; j++) {
                __half2 hq = *(__half2*)&qr[j];
                __half2 w = __hmul2(__hsub2(hq, hz[j]), hs[j]);
                o[j] = *(uint32_t*)&w;
            }
            *(uint4*)(g_W + (size_t)(k0 + i) * OUT_F + c * 8) = *(uint4*)o;
        }
    } else {
        size_t i = (size_t)((blockIdx.x - DEQ_BLOCKS) * 256 + threadIdx.x) * 4;
        float4 v = *(const float4*)(xf + i);
        __half h[4];
        h[0] = __float2half_rn(v.x); h[1] = __float2half_rn(v.y);
        h[2] = __float2half_rn(v.z); h[3] = __float2half_rn(v.w);
        *(uint2*)(g_X + i) = *(uint2*)h;
    }
}

// ---------------------------------------------------------------------------
// GEMM: 128x128x64, 256 thr, 2 CTAs/SM, 3-stage cp.async. Deferred + SPLIT
// tile loads: A-half at ks==1, B-half + commit at ks==2, with per-thread
// pointer-hoisted addressing.
// ---------------------------------------------------------------------------
__device__ __forceinline__ void cp16(uint32_t saddr, const void* gptr) {
    asm volatile("cp.async.cg.shared.global [%0], [%1], 16;\n"
                 :: "r"(saddr), "l"(gptr));
}
__device__ __forceinline__ void ldsm_x4(uint32_t& r0, uint32_t& r1,
                                        uint32_t& r2, uint32_t& r3, uint32_t a) {
    asm volatile("ldmatrix.sync.aligned.m8n8.x4.shared.b16 {%0,%1,%2,%3}, [%4];"
                 : "=r"(r0), "=r"(r1), "=r"(r2), "=r"(r3) : "r"(a));
}
__device__ __forceinline__ void ldsm_x4t(uint32_t& r0, uint32_t& r1,
                                         uint32_t& r2, uint32_t& r3, uint32_t a) {
    asm volatile("ldmatrix.sync.aligned.m8n8.x4.trans.shared.b16 {%0,%1,%2,%3}, [%4];"
                 : "=r"(r0), "=r"(r1), "=r"(r2), "=r"(r3) : "r"(a));
}

__global__ void __launch_bounds__(256, 2)
gemm_kernel(const float* __restrict__ biasf,
            float* __restrict__ out) {
    extern __shared__ __half smem[];
    __half* sA = smem;
    __half* sB = smem + STAGES * BM * LDA;

    const int t = threadIdx.x;

    const int NTILE = OUT_F / BN;  // 96
    const int SW = 8;
    int bid = blockIdx.x;
    int super = bid / (SW * NTILE);
    int r = bid - super * (SW * NTILE);
    const int bm = (super * SW + (r % SW)) * BM;
    const int bn = (r / SW) * BN;

    const uint32_t sA_base = (uint32_t)__cvta_generic_to_shared(sA);
    const uint32_t sB_base = (uint32_t)__cvta_generic_to_shared(sB);

    const int warp = t >> 5;
    const int lane = t & 31;
    const int wm = (warp & 3) * 32;
    const int wn = (warp >> 2) * 64;
    const int gr = lane >> 2;
    const int gc2 = (lane & 3) * 2;

    const int aRow = wm + (((lane >> 3) & 1) << 3) + (lane & 7);
    const int aCol = ((lane >> 4) << 3);
    const int bRow = (lane & 15);
    const int bCol = wn + ((lane >> 4) << 3);

    // Hoisted per-thread addressing: global pointers + smem write bases.
    const __half* pA = g_X + (size_t)(bm + (t >> 3)) * IN_F + (t & 7) * 8;
    const __half* pB = g_W + (size_t)(t >> 4) * OUT_F + bn + (t & 15) * 8;
    const uint32_t dA = sA_base + (uint32_t)(((t >> 3) * LDA + (t & 7) * 8) * 2);
    const uint32_t dB = sB_base + (uint32_t)(((t >> 4) * LDB + (t & 15) * 8) * 2);

    auto loadA = [&](int s, int k0) {
#pragma unroll
        for (int it = 0; it < 4; it++)
            cp16(dA + (uint32_t)(s * (BM * LDA * 2) + it * (32 * LDA * 2)),
                 pA + k0 + it * 32 * IN_F);
    };
    auto loadB = [&](int s, int k0) {
#pragma unroll
        for (int it = 0; it < 4; it++)
            cp16(dB + (uint32_t)(s * (BK * LDB * 2) + it * (16 * LDB * 2)),
                 pB + (size_t)k0 * OUT_F + it * 16 * OUT_F);
    };

    float acc[2][8][4];
#pragma unroll
    for (int mi = 0; mi < 2; mi++)
#pragma unroll
        for (int ni = 0; ni < 8; ni++)
#pragma unroll
            for (int i = 0; i < 4; i++) acc[mi][ni][i] = 0.f;

    loadA(0, 0); loadB(0, 0);
    asm volatile("cp.async.commit_group;\n" ::: "memory");
    loadA(1, BK); loadB(1, BK);
    asm volatile("cp.async.commit_group;\n" ::: "memory");

    for (int kt = 0; kt < KT; kt++) {
        if (kt < KT - 1) asm volatile("cp.async.wait_group 1;\n" ::: "memory");
        else             asm volatile("cp.async.wait_group 0;\n" ::: "memory");
        __syncthreads();

        const int s = kt % STAGES;
        const uint32_t aSt = sA_base + (uint32_t)(s * BM * LDA * 2);
        const uint32_t bSt = sB_base + (uint32_t)(s * BK * LDB * 2);
        const int s2 = (kt + 2) % STAGES;
        const int k2 = (kt + 2) * BK;
        const bool doLoad = (kt + 2 < KT);

        // A-fragment ks-pipeline.
        uint32_t a[2][2][4];
#pragma unroll
        for (int mi = 0; mi < 2; mi++) {
            uint32_t addr = aSt + (uint32_t)(((aRow + mi * 16) * LDA + aCol) * 2);
            ldsm_x4(a[0][mi][0], a[0][mi][1], a[0][mi][2], a[0][mi][3], addr);
        }

#pragma unroll
        for (int ks = 0; ks < 4; ks++) {
            const int kb = ks * 16;
            const int cur = ks & 1, nxt = cur ^ 1;

            // Split deferred tile load: A at ks==1, B + commit at ks==2.
            if (ks == 1 && doLoad) loadA(s2, k2);
            if (ks == 2 && doLoad) {
                loadB(s2, k2);
                asm volatile("cp.async.commit_group;\n" ::: "memory");
            }

            if (ks < 3) {
#pragma unroll
                for (int mi = 0; mi < 2; mi++) {
                    uint32_t addr = aSt +
                        (uint32_t)(((aRow + mi * 16) * LDA + aCol + kb + 16) * 2);
                    ldsm_x4(a[nxt][mi][0], a[nxt][mi][1],
                            a[nxt][mi][2], a[nxt][mi][3], addr);
                }
            }

            uint32_t b[8][2];
#pragma unroll
            for (int p = 0; p < 4; p++) {
                uint32_t addr = bSt +
                    (uint32_t)(((bRow + kb) * LDB + bCol + p * 16) * 2);
                ldsm_x4t(b[2 * p][0], b[2 * p][1],
                         b[2 * p + 1][0], b[2 * p + 1][1], addr);
            }

#pragma unroll
            for (int mi = 0; mi < 2; mi++)
#pragma unroll
                for (int ni = 0; ni < 8; ni++) {
                    asm volatile(
                        "mma.sync.aligned.m16n8k16.row.col.f32.f16.f16.f32 "
                        "{%0,%1,%2,%3}, {%4,%5,%6,%7}, {%8,%9}, {%0,%1,%2,%3};\n"
                        : "+f"(acc[mi][ni][0]), "+f"(acc[mi][ni][1]),
                          "+f"(acc[mi][ni][2]), "+f"(acc[mi][ni][3])
                        : "r"(a[cur][mi][0]), "r"(a[cur][mi][1]),
                          "r"(a[cur][mi][2]), "r"(a[cur][mi][3]),
                          "r"(b[ni][0]), "r"(b[ni][1]));
                }
        }
    }

    __half bh[16];
#pragma unroll
    for (int ni = 0; ni < 8; ni++) {
        bh[2 * ni]     = __float2half_rn(biasf[bn + wn + ni * 8 + gc2]);
        bh[2 * ni + 1] = __float2half_rn(biasf[bn + wn + ni * 8 + gc2 + 1]);
    }
#pragma unroll
    for (int mi = 0; mi < 2; mi++) {
        int row = bm + wm + mi * 16 + gr;
#pragma unroll
        for (int ni = 0; ni < 8; ni++) {
            int col = bn + wn + ni * 8 + gc2;
            float2 v;
            v.x = __half2float(__hadd(__float2half_rn(acc[mi][ni][0]), bh[2 * ni]));
            v.y = __half2float(__hadd(__float2half_rn(acc[mi][ni][1]), bh[2 * ni + 1]));
            *(float2*)(out + (size_t)row * OUT_F + col) = v;
            v.x = __half2float(__hadd(__float2half_rn(acc[mi][ni][2]), bh[2 * ni]));
            v.y = __half2float(__hadd(__float2half_rn(acc[mi][ni][3]), bh[2 * ni + 1]));
            *(float2*)(out + (size_t)(row + 8) * OUT_F + col) = v;
        }
    }
}

// ---------------------------------------------------------------------------
// Launch. Inputs resolved BY ELEMENT COUNT. fp16 tensors arrive as FLOAT32
// (harness upcast); output FLOAT32 [8192][12288].
// ---------------------------------------------------------------------------
extern "C" void kernel_launch(void* const* d_in, const int* in_sizes, int n_in,
                              void* d_out, int out_size) {
    const float* x      = nullptr;
    const int*   qw     = nullptr;
    const float* scales = nullptr;
    const int*   qz     = nullptr;
    const float* bias   = nullptr;

    for (int i = 0; i < n_in; i++) {
        switch (in_sizes[i]) {
            case 33554432: x      = (const float*)d_in[i]; break;
            case  6291456: qw     = (const int*)  d_in[i]; break;
            case   393216: scales = (const float*)d_in[i]; break;
            case    49152: qz     = (const int*)  d_in[i]; break;
            case    12288: bias   = (const float*)d_in[i]; break;
            default: break;
        }
    }
    float* out = (float*)d_out;

    prep_kernel<<<PREP_BLOCKS, 256>>>(x, qw, scales, qz);

    cudaFuncSetAttribute(gemm_kernel,
                         cudaFuncAttributeMaxDynamicSharedMemorySize, SMEM_BYTES);
    const int grid = (NTOK / BM) * (OUT_F / BN);  // 6144
    gemm_kernel<<<grid, 256, SMEM_BYTES>>>(bias, out);
}

// round 17
// speedup vs baseline: 1.2504x; 1.0415x over previous
#include <cuda_runtime.h>
#include <cuda_fp16.h>
#include <cstdint>

// Problem constants
#define IN_F   4096
#define OUT_F  12288
#define NWORDS 1536
#define NTOK   8192
#define GROUP  128

// GEMM tiling (converged shape)
#define BM 128
#define BN 128
#define BK 64
#define LDA 72     // BK + 8 halves pad (144B row: LDSM conflict-free)
#define LDB 136    // BN + 8 halves pad (272B row: LDSM conflict-free)
#define KT  (IN_F / BK)  // 64
#define STAGES 3
#define SMEM_BYTES (STAGES * (BM * LDA + BK * LDB) * 2)  // 107520 -> 2 CTAs/SM

// Prep kernel block split
#define DEQ_BLOCKS  3072
#define CONV_BLOCKS 32768
#define PREP_BLOCKS (DEQ_BLOCKS + CONV_BLOCKS)

__device__ __half g_X[(size_t)NTOK * IN_F];    // [M][K] fp16
__device__ __half g_W[(size_t)IN_F * OUT_F];   // [K][N] fp16

// ---------------------------------------------------------------------------
// int4x8 word -> 4x half2 {1024+n}, LOP3 magic + PRMT reorder.
// ---------------------------------------------------------------------------
__device__ __forceinline__ void unpack8(uint32_t q, uint32_t r[4]) {
    uint32_t p04, p15, p26, p37;
    asm("lop3.b32 %0, %1, 0x000F000F, 0x64006400, 0xEA;" : "=r"(p04) : "r"(q));
    asm("lop3.b32 %0, %1, 0x000F000F, 0x64006400, 0xEA;" : "=r"(p15) : "r"(q >> 4));
    asm("lop3.b32 %0, %1, 0x000F000F, 0x64006400, 0xEA;" : "=r"(p26) : "r"(q >> 8));
    asm("lop3.b32 %0, %1, 0x000F000F, 0x64006400, 0xEA;" : "=r"(p37) : "r"(q >> 12));
    asm("prmt.b32 %0, %1, %2, 0x5410;" : "=r"(r[0]) : "r"(p04), "r"(p15));
    asm("prmt.b32 %0, %1, %2, 0x5410;" : "=r"(r[1]) : "r"(p26), "r"(p37));
    asm("prmt.b32 %0, %1, %2, 0x7632;" : "=r"(r[2]) : "r"(p04), "r"(p15));
    asm("prmt.b32 %0, %1, %2, 0x7632;" : "=r"(r[3]) : "r"(p26), "r"(p37));
}

// ---------------------------------------------------------------------------
// Prep: blocks [0, DEQ_BLOCKS) dequantize W (bit-exact vs reference); rest
// convert X fp32->fp16 (exact).
// ---------------------------------------------------------------------------
__global__ void prep_kernel(const float* __restrict__ xf,
                            const int* __restrict__ qw,
                            const float* __restrict__ scales,
                            const int* __restrict__ qz) {
    if (blockIdx.x < DEQ_BLOCKS) {
        int tid = blockIdx.x * 256 + threadIdx.x;
        int c  = tid % NWORDS;
        int kb = tid / NWORDS;
        int k0 = kb * 8;
        int g  = kb >> 4;

        uint32_t zr[4];
        unpack8(((const uint32_t*)qz)[g * NWORDS + c], zr);
        __half2 hz[4];
        hz[0] = *(__half2*)&zr[0]; hz[1] = *(__half2*)&zr[1];
        hz[2] = *(__half2*)&zr[2]; hz[3] = *(__half2*)&zr[3];

        const float* sp = scales + (size_t)g * OUT_F + c * 8;
        float4 s0 = *(const float4*)sp;
        float4 s1 = *(const float4*)(sp + 4);
        __half2 hs[4];
        hs[0] = __floats2half2_rn(s0.x, s0.y);
        hs[1] = __floats2half2_rn(s0.z, s0.w);
        hs[2] = __floats2half2_rn(s1.x, s1.y);
        hs[3] = __floats2half2_rn(s1.z, s1.w);

#pragma unroll
        for (int i = 0; i < 8; i++) {
            uint32_t qr[4];
            unpack8(((const uint32_t*)qw)[(size_t)(k0 + i) * NWORDS + c], qr);
            uint32_t o[4];
#pragma unroll
            for (int j = 0; j < 4; j++) {
                __half2 hq = *(__half2*)&qr[j];
                __half2 w = __hmul2(__hsub2(hq, hz[j]), hs[j]);
                o[j] = *(uint32_t*)&w;
            }
            *(uint4*)(g_W + (size_t)(k0 + i) * OUT_F + c * 8) = *(uint4*)o;
        }
    } else {
        size_t i = (size_t)((blockIdx.x - DEQ_BLOCKS) * 256 + threadIdx.x) * 4;
        float4 v = *(const float4*)(xf + i);
        __half h[4];
        h[0] = __float2half_rn(v.x); h[1] = __float2half_rn(v.y);
        h[2] = __float2half_rn(v.z); h[3] = __float2half_rn(v.w);
        *(uint2*)(g_X + i) = *(uint2*)h;
    }
}

// ---------------------------------------------------------------------------
// GEMM: 128x128x64, 256 thr, 2 CTAs/SM, 3-stage cp.async. Deferred tile load
// split across THREE mma bursts: 4xA at ks==1, 2xB at ks==2, 2xB + commit at
// ks==3. Hoisted per-thread addressing.
// ---------------------------------------------------------------------------
__device__ __forceinline__ void cp16(uint32_t saddr, const void* gptr) {
    asm volatile("cp.async.cg.shared.global [%0], [%1], 16;\n"
                 :: "r"(saddr), "l"(gptr));
}
__device__ __forceinline__ void ldsm_x4(uint32_t& r0, uint32_t& r1,
                                        uint32_t& r2, uint32_t& r3, uint32_t a) {
    asm volatile("ldmatrix.sync.aligned.m8n8.x4.shared.b16 {%0,%1,%2,%3}, [%4];"
                 : "=r"(r0), "=r"(r1), "=r"(r2), "=r"(r3) : "r"(a));
}
__device__ __forceinline__ void ldsm_x4t(uint32_t& r0, uint32_t& r1,
                                         uint32_t& r2, uint32_t& r3, uint32_t a) {
    asm volatile("ldmatrix.sync.aligned.m8n8.x4.trans.shared.b16 {%0,%1,%2,%3}, [%4];"
                 : "=r"(r0), "=r"(r1), "=r"(r2), "=r"(r3) : "r"(a));
}

__global__ void __launch_bounds__(256, 2)
gemm_kernel(const float* __restrict__ biasf,
            float* __restrict__ out) {
    extern __shared__ __half smem[];
    __half* sA = smem;
    __half* sB = smem + STAGES * BM * LDA;

    const int t = threadIdx.x;

    const int NTILE = OUT_F / BN;  // 96
    const int SW = 8;
    int bid = blockIdx.x;
    int super = bid / (SW * NTILE);
    int r = bid - super * (SW * NTILE);
    const int bm = (super * SW + (r % SW)) * BM;
    const int bn = (r / SW) * BN;

    const uint32_t sA_base = (uint32_t)__cvta_generic_to_shared(sA);
    const uint32_t sB_base = (uint32_t)__cvta_generic_to_shared(sB);

    const int warp = t >> 5;
    const int lane = t & 31;
    const int wm = (warp & 3) * 32;
    const int wn = (warp >> 2) * 64;
    const int gr = lane >> 2;
    const int gc2 = (lane & 3) * 2;

    const int aRow = wm + (((lane >> 3) & 1) << 3) + (lane & 7);
    const int aCol = ((lane >> 4) << 3);
    const int bRow = (lane & 15);
    const int bCol = wn + ((lane >> 4) << 3);

    // Hoisted per-thread addressing: global pointers + smem write bases.
    const __half* pA = g_X + (size_t)(bm + (t >> 3)) * IN_F + (t & 7) * 8;
    const __half* pB = g_W + (size_t)(t >> 4) * OUT_F + bn + (t & 15) * 8;
    const uint32_t dA = sA_base + (uint32_t)(((t >> 3) * LDA + (t & 7) * 8) * 2);
    const uint32_t dB = sB_base + (uint32_t)(((t >> 4) * LDB + (t & 15) * 8) * 2);

    auto loadA = [&](int s, int k0) {
#pragma unroll
        for (int it = 0; it < 4; it++)
            cp16(dA + (uint32_t)(s * (BM * LDA * 2) + it * (32 * LDA * 2)),
                 pA + k0 + it * 32 * IN_F);
    };
    auto loadBlo = [&](int s, int k0) {
#pragma unroll
        for (int it = 0; it < 2; it++)
            cp16(dB + (uint32_t)(s * (BK * LDB * 2) + it * (16 * LDB * 2)),
                 pB + (size_t)k0 * OUT_F + it * 16 * OUT_F);
    };
    auto loadBhi = [&](int s, int k0) {
#pragma unroll
        for (int it = 2; it < 4; it++)
            cp16(dB + (uint32_t)(s * (BK * LDB * 2) + it * (16 * LDB * 2)),
                 pB + (size_t)k0 * OUT_F + it * 16 * OUT_F);
    };

    float acc[2][8][4];
#pragma unroll
    for (int mi = 0; mi < 2; mi++)
#pragma unroll
        for (int ni = 0; ni < 8; ni++)
#pragma unroll
            for (int i = 0; i < 4; i++) acc[mi][ni][i] = 0.f;

    loadA(0, 0); loadBlo(0, 0); loadBhi(0, 0);
    asm volatile("cp.async.commit_group;\n" ::: "memory");
    loadA(1, BK); loadBlo(1, BK); loadBhi(1, BK);
    asm volatile("cp.async.commit_group;\n" ::: "memory");

    for (int kt = 0; kt < KT; kt++) {
        if (kt < KT - 1) asm volatile("cp.async.wait_group 1;\n" ::: "memory");
        else             asm volatile("cp.async.wait_group 0;\n" ::: "memory");
        __syncthreads();

        const int s = kt % STAGES;
        const uint32_t aSt = sA_base + (uint32_t)(s * BM * LDA * 2);
        const uint32_t bSt = sB_base + (uint32_t)(s * BK * LDB * 2);
        const int s2 = (kt + 2) % STAGES;
        const int k2 = (kt + 2) * BK;
        const bool doLoad = (kt + 2 < KT);

        // A-fragment ks-pipeline.
        uint32_t a[2][2][4];
#pragma unroll
        for (int mi = 0; mi < 2; mi++) {
            uint32_t addr = aSt + (uint32_t)(((aRow + mi * 16) * LDA + aCol) * 2);
            ldsm_x4(a[0][mi][0], a[0][mi][1], a[0][mi][2], a[0][mi][3], addr);
        }

#pragma unroll
        for (int ks = 0; ks < 4; ks++) {
            const int kb = ks * 16;
            const int cur = ks & 1, nxt = cur ^ 1;

            // Deferred tile load split across three bursts.
            if (ks == 1 && doLoad) loadA(s2, k2);
            if (ks == 2 && doLoad) loadBlo(s2, k2);
            if (ks == 3 && doLoad) {
                loadBhi(s2, k2);
                asm volatile("cp.async.commit_group;\n" ::: "memory");
            }

            if (ks < 3) {
#pragma unroll
                for (int mi = 0; mi < 2; mi++) {
                    uint32_t addr = aSt +
                        (uint32_t)(((aRow + mi * 16) * LDA + aCol + kb + 16) * 2);
                    ldsm_x4(a[nxt][mi][0], a[nxt][mi][1],
                            a[nxt][mi][2], a[nxt][mi][3], addr);
                }
            }

            uint32_t b[8][2];
#pragma unroll
            for (int p = 0; p < 4; p++) {
                uint32_t addr = bSt +
                    (uint32_t)(((bRow + kb) * LDB + bCol + p * 16) * 2);
                ldsm_x4t(b[2 * p][0], b[2 * p][1],
                         b[2 * p + 1][0], b[2 * p + 1][1], addr);
            }

#pragma unroll
            for (int mi = 0; mi < 2; mi++)
#pragma unroll
                for (int ni = 0; ni < 8; ni++) {
                    asm volatile(
                        "mma.sync.aligned.m16n8k16.row.col.f32.f16.f16.f32 "
                        "{%0,%1,%2,%3}, {%4,%5,%6,%7}, {%8,%9}, {%0,%1,%2,%3};\n"
                        : "+f"(acc[mi][ni][0]), "+f"(acc[mi][ni][1]),
                          "+f"(acc[mi][ni][2]), "+f"(acc[mi][ni][3])
                        : "r"(a[cur][mi][0]), "r"(a[cur][mi][1]),
                          "r"(a[cur][mi][2]), "r"(a[cur][mi][3]),
                          "r"(b[ni][0]), "r"(b[ni][1]));
                }
        }
    }

    __half bh[16];
#pragma unroll
    for (int ni = 0; ni < 8; ni++) {
        bh[2 * ni]     = __float2half_rn(biasf[bn + wn + ni * 8 + gc2]);
        bh[2 * ni + 1] = __float2half_rn(biasf[bn + wn + ni * 8 + gc2 + 1]);
    }
#pragma unroll
    for (int mi = 0; mi < 2; mi++) {
        int row = bm + wm + mi * 16 + gr;
#pragma unroll
        for (int ni = 0; ni < 8; ni++) {
            int col = bn + wn + ni * 8 + gc2;
            float2 v;
            v.x = __half2float(__hadd(__float2half_rn(acc[mi][ni][0]), bh[2 * ni]));
            v.y = __half2float(__hadd(__float2half_rn(acc[mi][ni][1]), bh[2 * ni + 1]));
            *(float2*)(out + (size_t)row * OUT_F + col) = v;
            v.x = __half2float(__hadd(__float2half_rn(acc[mi][ni][2]), bh[2 * ni]));
            v.y = __half2float(__hadd(__float2half_rn(acc[mi][ni][3]), bh[2 * ni + 1]));
            *(float2*)(out + (size_t)(row + 8) * OUT_F + col) = v;
        }
    }
}

// ---------------------------------------------------------------------------
// Launch. Inputs resolved BY ELEMENT COUNT. fp16 tensors arrive as FLOAT32
// (harness upcast); output FLOAT32 [8192][12288].
// ---------------------------------------------------------------------------
extern "C" void kernel_launch(void* const* d_in, const int* in_sizes, int n_in,
                              void* d_out, int out_size) {
    const float* x      = nullptr;
    const int*   qw     = nullptr;
    const float* scales = nullptr;
    const int*   qz     = nullptr;
    const float* bias   = nullptr;

    for (int i = 0; i < n_in; i++) {
        switch (in_sizes[i]) {
            case 33554432: x      = (const float*)d_in[i]; break;
            case  6291456: qw     = (const int*)  d_in[i]; break;
            case   393216: scales = (const float*)d_in[i]; break;
            case    49152: qz     = (const int*)  d_in[i]; break;
            case    12288: bias   = (const float*)d_in[i]; break;
            default: break;
        }
    }
    float* out = (float*)d_out;

    prep_kernel<<<PREP_BLOCKS, 256>>>(x, qw, scales, qz);

    cudaFuncSetAttribute(gemm_kernel,
                         cudaFuncAttributeMaxDynamicSharedMemorySize, SMEM_BYTES);
    const int grid = (NTOK / BM) * (OUT_F / BN);  // 6144
    gemm_kernel<<<grid, 256, SMEM_BYTES>>>(bias, out);
}